// round 16
// baseline (speedup 1.0000x reference)
#include <cuda_runtime.h>

#define B 8
#define S 64
#define V 50257
#define P 200
#define NSEG 2
#define GRID (B * S * NSEG)       // 1024 CTAs, one wave at 7 CTAs/SM
#define THREADS 256
#define TILE_G 512                // float4 groups per tile = 8 KB
#define NBUF 2
#define INV_T  (1.0f/0.6f)
#define PEN    1.2f
#define INV_PEN (1.0f/1.2f)

__device__ float g_pl[GRID];      // per-(row,seg) partial sums (penalty included)

struct __align__(16) Smem {
    float4 buf[NBUF][TILE_G];     // 16 KB double buffer
    unsigned long long mbar[NBUF];
    int sprev[P];
    float red[THREADS / 32];
    float sR;
};

__device__ __forceinline__ unsigned su32(const void* p) {
    return (unsigned)__cvta_generic_to_shared(p);
}
__device__ __forceinline__ void mbar_init(unsigned addr, unsigned count) {
    asm volatile("mbarrier.init.shared.b64 [%0], %1;" :: "r"(addr), "r"(count) : "memory");
}
__device__ __forceinline__ void mbar_expect_tx(unsigned addr, unsigned bytes) {
    asm volatile("mbarrier.arrive.expect_tx.shared.b64 _, [%0], %1;"
                 :: "r"(addr), "r"(bytes) : "memory");
}
__device__ __forceinline__ void bulk_g2s(unsigned dst, const void* src,
                                         unsigned bytes, unsigned mbar) {
    asm volatile("cp.async.bulk.shared::cluster.global.mbarrier::complete_tx::bytes "
                 "[%0], [%1], %2, [%3];"
                 :: "r"(dst), "l"(src), "r"(bytes), "r"(mbar) : "memory");
}
__device__ __forceinline__ void mbar_wait(unsigned addr, unsigned parity) {
    asm volatile(
        "{\n\t.reg .pred p;\n\t"
        "LAB_W%=:\n\t"
        "mbarrier.try_wait.parity.acquire.cta.shared::cta.b64 p, [%0], %1;\n\t"
        "@p bra LAB_D%=;\n\t"
        "bra LAB_W%=;\n\t"
        "LAB_D%=:\n\t}"
        :: "r"(addr), "r"(parity) : "memory");
}

// all_neg over the 8 batch rows at (s, v); rare path (~0.4% of positions).
__device__ __forceinline__ float pfac(const float* __restrict__ logits, int s, int v) {
    bool an = true;
#pragma unroll
    for (int bb = 0; bb < B; bb++)
        an = an && (logits[((size_t)bb * S + s) * V + v] < 0.0f);
    return (an ? PEN : INV_PEN) * INV_T;
}

// Shared geometry: row p = b*S+s; a aligns (p*V + a) to 16B; seg owns groups [g0, g1).
struct Geo { int a, Gtot, g0, g1, ng, ntiles; };
__device__ __forceinline__ Geo geo(int p, int seg) {
    Geo g;
    g.a = (4 - (p & 3)) & 3;
    g.Gtot = (V - g.a) >> 2;
    g.g0 = seg * g.Gtot / NSEG;
    g.g1 = (seg + 1) * g.Gtot / NSEG;
    g.ng = g.g1 - g.g0;
    g.ntiles = (g.ng + TILE_G - 1) / TILE_G;
    return g;
}

// ---------------- Pass A: bulk-pipelined sums of exp(penalized/T) ----------
__global__ __launch_bounds__(THREADS, 7) void k_passA(const float* __restrict__ logits,
                                                      const int* __restrict__ prev) {
    __shared__ Smem sm;
    const int seg = blockIdx.x & (NSEG - 1);
    const int p = blockIdx.x >> 1;
    const int s = p % S;
    const int tid = threadIdx.x;
    const Geo g = geo(p, seg);
    const size_t rowoff = (size_t)p * V;
    const float4* src = (const float4*)(logits + rowoff + g.a) + g.g0;

    if (tid == 0) {
        mbar_init(su32(&sm.mbar[0]), 1);
        mbar_init(su32(&sm.mbar[1]), 1);
    }
    if (tid < P) sm.sprev[tid] = prev[s * P + tid];
    __syncthreads();

    if (tid == 0) {
        const unsigned bytes0 = (unsigned)((g.ng < TILE_G ? g.ng : TILE_G) * 16);
        mbar_expect_tx(su32(&sm.mbar[0]), bytes0);
        bulk_g2s(su32(&sm.buf[0][0]), (const void*)src, bytes0, su32(&sm.mbar[0]));
    }

    float sum = 0.0f;
    for (int i = 0; i < g.ntiles; i++) {
        if (i + 1 < g.ntiles && tid == 0) {
            const int gbase = (i + 1) * TILE_G;
            const int rem = g.ng - gbase;
            const unsigned bytes = (unsigned)((rem < TILE_G ? rem : TILE_G) * 16);
            const int bb = (i + 1) & 1;
            mbar_expect_tx(su32(&sm.mbar[bb]), bytes);
            bulk_g2s(su32(&sm.buf[bb][0]), (const void*)(src + gbase), bytes,
                     su32(&sm.mbar[bb]));
        }
        mbar_wait(su32(&sm.mbar[i & 1]), (i >> 1) & 1);
        const int gcnt = (g.ng - i * TILE_G < TILE_G) ? (g.ng - i * TILE_G) : TILE_G;
        const float4* sb = sm.buf[i & 1];
        for (int j = tid; j < gcnt; j += THREADS) {
            const float4 x = sb[j];
            sum += __expf(x.x * INV_T) + __expf(x.y * INV_T)
                 + __expf(x.z * INV_T) + __expf(x.w * INV_T);
        }
        __syncthreads();
    }

    // sparse penalty corrections for this seg's range (dedup'd tokens)
    {
        const int vlo = g.a + 4 * g.g0, vhi = g.a + 4 * g.g1;
        if (tid < P) {
            const int tok = sm.sprev[tid];
            if (tok >= vlo && tok < vhi) {
                bool uniq = true;
                for (int j = 0; j < tid; j++) uniq &= (sm.sprev[j] != tok);
                if (uniq) {
                    const float x = logits[rowoff + tok];
                    const float fac = pfac(logits, s, tok);
                    sum += __expf(x * fac) - __expf(x * INV_T);
                }
            }
        }
    }
    // unaligned head/tail scalars, seg 0 only (cnt <= 5)
    if (seg == 0) {
        const int tail0 = g.a + 4 * g.Gtot;
        const int cnt = g.a + (V - tail0);
        if (tid < cnt) {
            const int v = (tid < g.a) ? tid : tail0 + (tid - g.a);
            bool hit = false;
            for (int j = 0; j < P; j++) hit |= (sm.sprev[j] == v);
            const float fac = hit ? pfac(logits, s, v) : INV_T;
            sum += __expf(logits[rowoff + v] * fac);
        }
    }

#pragma unroll
    for (int off = 16; off; off >>= 1)
        sum += __shfl_xor_sync(0xffffffffu, sum, off);
    if ((tid & 31) == 0) sm.red[tid >> 5] = sum;
    __syncthreads();
    if (tid == 0) {
        float L = 0.0f;
#pragma unroll
        for (int w = 0; w < THREADS / 32; w++) L += sm.red[w];
        g_pl[blockIdx.x] = L;
    }
}

// ---------------- Pass C: bulk-pipelined normalize + write ----------------
__global__ __launch_bounds__(THREADS, 7) void k_passC(const float* __restrict__ logits,
                                                      const int* __restrict__ prev,
                                                      float* __restrict__ out) {
    __shared__ Smem sm;
    const int seg = blockIdx.x & (NSEG - 1);
    const int p = blockIdx.x >> 1;
    const int s = p % S;
    const int tid = threadIdx.x;
    const Geo g = geo(p, seg);
    const size_t rowoff = (size_t)p * V;
    const float4* src = (const float4*)(logits + rowoff + g.a) + g.g0;
    float4* dst = (float4*)(out + rowoff + g.a) + g.g0;

    if (tid == 0) {
        mbar_init(su32(&sm.mbar[0]), 1);
        mbar_init(su32(&sm.mbar[1]), 1);
        sm.sR = 1.0f / (g_pl[p * NSEG] + g_pl[p * NSEG + 1]);
    }
    if (tid < P) sm.sprev[tid] = prev[s * P + tid];
    __syncthreads();
    const float R = sm.sR;

    if (tid == 0) {
        const unsigned bytes0 = (unsigned)((g.ng < TILE_G ? g.ng : TILE_G) * 16);
        mbar_expect_tx(su32(&sm.mbar[0]), bytes0);
        bulk_g2s(su32(&sm.buf[0][0]), (const void*)src, bytes0, su32(&sm.mbar[0]));
    }

    for (int i = 0; i < g.ntiles; i++) {
        if (i + 1 < g.ntiles && tid == 0) {
            const int gbase = (i + 1) * TILE_G;
            const int rem = g.ng - gbase;
            const unsigned bytes = (unsigned)((rem < TILE_G ? rem : TILE_G) * 16);
            const int bb = (i + 1) & 1;
            mbar_expect_tx(su32(&sm.mbar[bb]), bytes);
            bulk_g2s(su32(&sm.buf[bb][0]), (const void*)(src + gbase), bytes,
                     su32(&sm.mbar[bb]));
        }
        mbar_wait(su32(&sm.mbar[i & 1]), (i >> 1) & 1);
        const int gcnt = (g.ng - i * TILE_G < TILE_G) ? (g.ng - i * TILE_G) : TILE_G;
        const float4* sb = sm.buf[i & 1];
        float4* dt = dst + i * TILE_G;
        for (int j = tid; j < gcnt; j += THREADS) {
            const float4 x = sb[j];
            float4 o;
            o.x = __expf(x.x * INV_T) * R;
            o.y = __expf(x.y * INV_T) * R;
            o.z = __expf(x.z * INV_T) * R;
            o.w = __expf(x.w * INV_T) * R;
            __stcs(dt + j, o);
        }
        __syncthreads();
    }

    // overwrite masked positions (fast writes above are ordered by the final
    // __syncthreads of the tile loop; each position is within this CTA's seg)
    {
        const int vlo = g.a + 4 * g.g0, vhi = g.a + 4 * g.g1;
        if (tid < P) {
            const int tok = sm.sprev[tid];
            if (tok >= vlo && tok < vhi) {
                bool uniq = true;
                for (int j = 0; j < tid; j++) uniq &= (sm.sprev[j] != tok);
                if (uniq) {
                    const float x = logits[rowoff + tok];
                    const float fac = pfac(logits, s, tok);
                    out[rowoff + tok] = __expf(x * fac) * R;
                }
            }
        }
    }
    if (seg == 0) {
        const int tail0 = g.a + 4 * g.Gtot;
        const int cnt = g.a + (V - tail0);
        if (tid < cnt) {
            const int v = (tid < g.a) ? tid : tail0 + (tid - g.a);
            bool hit = false;
            for (int j = 0; j < P; j++) hit |= (sm.sprev[j] == v);
            const float fac = hit ? pfac(logits, s, v) : INV_T;
            out[rowoff + v] = __expf(logits[rowoff + v] * fac) * R;
        }
    }
}

extern "C" void kernel_launch(void* const* d_in, const int* in_sizes, int n_in,
                              void* d_out, int out_size) {
    const float* logits = (const float*)d_in[0];
    const int* prev = (const int*)d_in[1];
    float* out = (float*)d_out;
    (void)in_sizes; (void)n_in; (void)out_size;

    k_passA<<<GRID, THREADS>>>(logits, prev);
    k_passC<<<GRID, THREADS>>>(logits, prev, out);
}

// round 17
// speedup vs baseline: 1.1596x; 1.1596x over previous
#include <cuda_runtime.h>

#define B 8
#define S 64
#define SHALF 32
#define V 50257
#define P 200
#define NCHUNK 18
#define THREADS 256
#define MWORDS 96             // chunk span <= ~2800 floats -> 88 words, padded
#define INV_T  (1.0f/0.6f)
#define PEN    1.2f
#define INV_PEN (1.0f/1.2f)
#define BSTRIDE  ((size_t)S * V)       // 3216448 (divisible by 4)
#define BSTRIDE4 (BSTRIDE / 4)

__device__ float g_pl[S * NCHUNK * B];

// Aligned vector range for (s, chunk c): v = a + 4g is 16B-aligned for every
// batch row (since (b*S+s)*V ≡ s mod 4 and BSTRIDE % 4 == 0).
__device__ __forceinline__ void chunk_range(int s, int c, int& a, int& G, int& v0, int& v1) {
    a = (4 - (s & 3)) & 3;
    G = (V - a) >> 2;
    const int g0 = (int)(((long long)c * G) / NCHUNK);
    const int g1 = (int)(((long long)(c + 1) * G) / NCHUNK);
    v0 = a + 4 * g0;
    v1 = a + 4 * g1;
}

__device__ __forceinline__ void build_mask(unsigned* smask, int* sprev,
                                           const int* __restrict__ prev,
                                           int s, int v0, int v1) {
    for (int i = threadIdx.x; i < MWORDS; i += THREADS) smask[i] = 0u;
    __syncthreads();
    for (int t = threadIdx.x; t < P; t += THREADS) {
        const int tok = prev[s * P + t];
        sprev[t] = tok;
        if (tok >= v0 && tok < v1) {
            const int r = tok - v0;
            atomicOr(&smask[r >> 5], 1u << (r & 31));
        }
    }
}

// Pass A: partial sums of exp(penalized * 1/T) per (s, chunk, b).
__global__ __launch_bounds__(THREADS, 4) void k_passA(const float* __restrict__ logits,
                                                      const int* __restrict__ prev,
                                                      int s0) {
    const int c = blockIdx.x % NCHUNK;
    const int s = s0 + blockIdx.x / NCHUNK;
    int a, G, v0, v1;
    chunk_range(s, c, a, G, v0, v1);

    __shared__ unsigned smask[MWORDS];
    __shared__ int sprev[P];
    build_mask(smask, sprev, prev, s, v0, v1);
    __syncthreads();

    const float* base = logits + (size_t)s * V;
    float sum[B];
#pragma unroll
    for (int b = 0; b < B; b++) sum[b] = 0.0f;

    for (int v = v0 + 4 * (int)threadIdx.x; v < v1; v += 4 * THREADS) {
        const int r = v - v0;
        const unsigned bits4 = (smask[r >> 5] >> (r & 31)) & 0xFu;
        const float4* p = (const float4*)(base + v);
        float4 x[B];
#pragma unroll
        for (int b = 0; b < B; b++) x[b] = p[(size_t)b * BSTRIDE4];
        float4 mx = x[0];
#pragma unroll
        for (int b = 1; b < B; b++) {
            mx.x = fmaxf(mx.x, x[b].x); mx.y = fmaxf(mx.y, x[b].y);
            mx.z = fmaxf(mx.z, x[b].z); mx.w = fmaxf(mx.w, x[b].w);
        }
        float fac[4];
        fac[0] = ((bits4 & 1u) ? (mx.x < 0.0f ? PEN : INV_PEN) : 1.0f) * INV_T;
        fac[1] = ((bits4 & 2u) ? (mx.y < 0.0f ? PEN : INV_PEN) : 1.0f) * INV_T;
        fac[2] = ((bits4 & 4u) ? (mx.z < 0.0f ? PEN : INV_PEN) : 1.0f) * INV_T;
        fac[3] = ((bits4 & 8u) ? (mx.w < 0.0f ? PEN : INV_PEN) : 1.0f) * INV_T;
#pragma unroll
        for (int b = 0; b < B; b++)
            sum[b] += __expf(x[b].x * fac[0]) + __expf(x[b].y * fac[1])
                    + __expf(x[b].z * fac[2]) + __expf(x[b].w * fac[3]);
    }

    // chunk 0 handles the <=6 unaligned scalar elements (head [0,a), tail [a+4G, V))
    if (c == 0) {
        const int tail0 = a + 4 * G;
        const int cnt = a + (V - tail0);
        if ((int)threadIdx.x < cnt) {
            const int v = ((int)threadIdx.x < a) ? (int)threadIdx.x
                                                 : tail0 + ((int)threadIdx.x - a);
            bool hit = false;
            for (int t = 0; t < P; t++) hit |= (sprev[t] == v);
            float x[B];
            bool allneg = true;
#pragma unroll
            for (int b = 0; b < B; b++) {
                x[b] = base[(size_t)b * BSTRIDE + v];
                allneg = allneg && (x[b] < 0.0f);
            }
            const float fac = (hit ? (allneg ? PEN : INV_PEN) : 1.0f) * INV_T;
#pragma unroll
            for (int b = 0; b < B; b++) sum[b] += __expf(x[b] * fac);
        }
    }

    // block reduce
#pragma unroll
    for (int b = 0; b < B; b++) {
#pragma unroll
        for (int off = 16; off; off >>= 1)
            sum[b] += __shfl_xor_sync(0xffffffffu, sum[b], off);
    }
    __shared__ float ssum[THREADS / 32][B];
    const int warp = threadIdx.x >> 5;
    const int lane = threadIdx.x & 31;
    if (lane == 0) {
#pragma unroll
        for (int b = 0; b < B; b++) ssum[warp][b] = sum[b];
    }
    __syncthreads();
    if (threadIdx.x < B) {
        const int b = threadIdx.x;
        float L = 0.0f;
#pragma unroll
        for (int w = 0; w < THREADS / 32; w++) L += ssum[w][b];
        g_pl[(s * NCHUNK + c) * B + b] = L;
    }
}

// Pass C: inline chunk-reduce, recompute penalized exp, normalize, stream out.
__global__ __launch_bounds__(THREADS, 4) void k_passC(const float* __restrict__ logits,
                                                      const int* __restrict__ prev,
                                                      float* __restrict__ out,
                                                      int s0) {
    const int c = blockIdx.x % NCHUNK;
    const int s = s0 + blockIdx.x / NCHUNK;
    int a, G, v0, v1;
    chunk_range(s, c, a, G, v0, v1);

    __shared__ unsigned smask[MWORDS];
    __shared__ int sprev[P];
    __shared__ float sR[B];
    build_mask(smask, sprev, prev, s, v0, v1);
    if (threadIdx.x < B) {
        float L = 0.0f;
#pragma unroll
        for (int cc = 0; cc < NCHUNK; cc++)
            L += g_pl[(s * NCHUNK + cc) * B + threadIdx.x];
        sR[threadIdx.x] = 1.0f / L;
    }
    __syncthreads();

    float R[B];
#pragma unroll
    for (int b = 0; b < B; b++) R[b] = sR[b];

    const float* base = logits + (size_t)s * V;
    float* obase = out + (size_t)s * V;

    for (int v = v0 + 4 * (int)threadIdx.x; v < v1; v += 4 * THREADS) {
        const int r = v - v0;
        const unsigned bits4 = (smask[r >> 5] >> (r & 31)) & 0xFu;
        const float4* p = (const float4*)(base + v);
        float4* q = (float4*)(obase + v);
        float4 x[B];
#pragma unroll
        for (int b = 0; b < B; b++) x[b] = p[(size_t)b * BSTRIDE4];   // short-distance L2 hit
        float4 mx = x[0];
#pragma unroll
        for (int b = 1; b < B; b++) {
            mx.x = fmaxf(mx.x, x[b].x); mx.y = fmaxf(mx.y, x[b].y);
            mx.z = fmaxf(mx.z, x[b].z); mx.w = fmaxf(mx.w, x[b].w);
        }
        float fac[4];
        fac[0] = ((bits4 & 1u) ? (mx.x < 0.0f ? PEN : INV_PEN) : 1.0f) * INV_T;
        fac[1] = ((bits4 & 2u) ? (mx.y < 0.0f ? PEN : INV_PEN) : 1.0f) * INV_T;
        fac[2] = ((bits4 & 4u) ? (mx.z < 0.0f ? PEN : INV_PEN) : 1.0f) * INV_T;
        fac[3] = ((bits4 & 8u) ? (mx.w < 0.0f ? PEN : INV_PEN) : 1.0f) * INV_T;
#pragma unroll
        for (int b = 0; b < B; b++) {
            float4 o;
            o.x = __expf(x[b].x * fac[0]) * R[b];
            o.y = __expf(x[b].y * fac[1]) * R[b];
            o.z = __expf(x[b].z * fac[2]) * R[b];
            o.w = __expf(x[b].w * fac[3]) * R[b];
            __stcs(q + (size_t)b * BSTRIDE4, o);        // evict-first: protect logits in L2
        }
    }

    if (c == 0) {
        const int tail0 = a + 4 * G;
        const int cnt = a + (V - tail0);
        if ((int)threadIdx.x < cnt) {
            const int v = ((int)threadIdx.x < a) ? (int)threadIdx.x
                                                 : tail0 + ((int)threadIdx.x - a);
            bool hit = false;
            for (int t = 0; t < P; t++) hit |= (sprev[t] == v);
            float x[B];
            bool allneg = true;
#pragma unroll
            for (int b = 0; b < B; b++) {
                x[b] = base[(size_t)b * BSTRIDE + v];
                allneg = allneg && (x[b] < 0.0f);
            }
            const float fac = (hit ? (allneg ? PEN : INV_PEN) : 1.0f) * INV_T;
#pragma unroll
            for (int b = 0; b < B; b++)
                obase[(size_t)b * BSTRIDE + v] = __expf(x[b] * fac) * R[b];
        }
    }
}

extern "C" void kernel_launch(void* const* d_in, const int* in_sizes, int n_in,
                              void* d_out, int out_size) {
    const float* logits = (const float*)d_in[0];
    const int* prev = (const int*)d_in[1];
    float* out = (float*)d_out;
    (void)in_sizes; (void)n_in; (void)out_size;

    // Half-by-half: each C re-reads logits its paired A just loaded (short L2
    // reuse distance), instead of a full-tensor distance.
    k_passA<<<SHALF * NCHUNK, THREADS>>>(logits, prev, 0);
    k_passC<<<SHALF * NCHUNK, THREADS>>>(logits, prev, out, 0);
    k_passA<<<SHALF * NCHUNK, THREADS>>>(logits, prev, SHALF);
    k_passC<<<SHALF * NCHUNK, THREADS>>>(logits, prev, out, SHALF);
}